// round 15
// baseline (speedup 1.0000x reference)
#include <cuda_runtime.h>
#include <cuda_fp16.h>
#include <math.h>
#include <stdint.h>

#define DIMC 384
#define NHEADS 6
#define HD 64
#define WINS 14
#define NWIN 24
#define NW 576
#define LW 196
#define TOK (NW*LW)      // 112896
#define WH (NW*NHEADS)   // 3456
#define LL (LW*LW)
#define HIDDEN 1536
#define LN_EPS 1e-5f
#define ATT_SCALE 0.125f

#define SCORE_SMEM ((64*200*2 + LW*WINS*2) * 4)
#define AV_SMEM ((LW*HD + LL) * 4)

// ---------------- mma.sync GEMM geometry -----------------------------------
#define TMM 128
#define TNN 128
#define KC 32                       // fp16 K per chunk
#define TILE_B 8192                 // 128 rows * 64 B
#define STAGE_B (3 * TILE_B)        // Ah, Al, B  (B has no lo plane)
#define NSTAGE 3
#define GEMM_SMEM (NSTAGE * STAGE_B)  // 73728

// ---------------- scratch --------------------------------------------------
__device__ float g_q[(size_t)TOK * DIMC];
__device__ float g_k[(size_t)TOK * DIMC];
__device__ float g_v[(size_t)TOK * DIMC];
__device__ float g_P[(size_t)WH * LL];
__device__ float g_x2[(size_t)TOK * DIMC];
__device__ __half g_sa_hi[(size_t)TOK * DIMC];
__device__ __half g_sa_lo[(size_t)TOK * DIMC];
__device__ __half g_ba_hi[(size_t)TOK * HIDDEN];
__device__ __half g_ba_lo[(size_t)TOK * HIDDEN];
// transposed fp16 weights [N][K]
__device__ __half g_wqkv[1152 * 384];
__device__ __half g_wproj[384 * 384];
__device__ __half g_wfc1[1536 * 384];
__device__ __half g_wfc2[384 * 1536];

// ---------------- PTX helpers ----------------------------------------------
__device__ __forceinline__ uint32_t smem_u32(const void* p)
{ return (uint32_t)__cvta_generic_to_shared(p); }

__device__ __forceinline__ void cp16(uint32_t dst, const void* src)
{ asm volatile("cp.async.cg.shared.global [%0], [%1], 16;" :: "r"(dst), "l"(src)); }
__device__ __forceinline__ void cp_commit()
{ asm volatile("cp.async.commit_group;" ::: "memory"); }
template <int N> __device__ __forceinline__ void cp_wait()
{ asm volatile("cp.async.wait_group %0;" :: "n"(N) : "memory"); }

__device__ __forceinline__ void ldsm4(uint32_t* r, uint32_t a)
{
    asm volatile("ldmatrix.sync.aligned.m8n8.x4.shared.b16 {%0,%1,%2,%3}, [%4];"
                 : "=r"(r[0]), "=r"(r[1]), "=r"(r[2]), "=r"(r[3]) : "r"(a));
}

__device__ __forceinline__ void mma16816(float* c, const uint32_t* a, uint32_t b0, uint32_t b1)
{
    asm volatile("mma.sync.aligned.m16n8k16.row.col.f32.f16.f16.f32 "
                 "{%0,%1,%2,%3}, {%4,%5,%6,%7}, {%8,%9}, {%0,%1,%2,%3};"
                 : "+f"(c[0]), "+f"(c[1]), "+f"(c[2]), "+f"(c[3])
                 : "r"(a[0]), "r"(a[1]), "r"(a[2]), "r"(a[3]), "r"(b0), "r"(b1));
}

__device__ __forceinline__ float gelu_exact(float v)
{ return 0.5f * v * (1.0f + erff(v * 0.70710678118654752f)); }

// swizzled byte offset within one 128x(64B) tile
__device__ __forceinline__ uint32_t tswz(int r, int cc)
{ return (uint32_t)(r * 64 + ((cc ^ ((r >> 1) & 3)) << 4)); }

// -------- fused weight transpose -> fp16 wT[n][k] (all four weights) -------
// tiles: qkv 432, proj 144, fc1 576, fc2 576  (32x32 tiles)
__global__ void __launch_bounds__(256)
transpose_all(const float* __restrict__ w0, const float* __restrict__ w1,
              const float* __restrict__ w2, const float* __restrict__ w3)
{
    __shared__ float tile[32][33];
    int bid = blockIdx.x;
    const float* src; __half* dst; int K, N, local;
    if (bid < 432)       { src = w0; dst = g_wqkv;  K = 384;  N = 1152; local = bid; }
    else if (bid < 576)  { src = w1; dst = g_wproj; K = 384;  N = 384;  local = bid - 432; }
    else if (bid < 1152) { src = w2; dst = g_wfc1;  K = 384;  N = 1536; local = bid - 576; }
    else                 { src = w3; dst = g_wfc2;  K = 1536; N = 384;  local = bid - 1152; }
    int ntn = N / 32;
    int by = local / ntn, bx = local % ntn;
    int tx = threadIdx.x & 31, ty = threadIdx.x >> 5;
    #pragma unroll
    for (int i = 0; i < 4; i++) {
        int k = by * 32 + ty + i * 8;
        int n = bx * 32 + tx;
        tile[ty + i * 8][tx] = src[(size_t)k * N + n];
    }
    __syncthreads();
    #pragma unroll
    for (int i = 0; i < 4; i++) {
        int n = bx * 32 + ty + i * 8;
        int k = by * 32 + tx;
        dst[(size_t)n * K + k] = __float2half(tile[tx][ty + i * 8]);
    }
}

// ---------------- LayerNorm -> fp16 hi/lo pair -----------------------------
__global__ void ln_kernel(const float* __restrict__ in, const float* __restrict__ w,
                          const float* __restrict__ b,
                          __half* __restrict__ out_hi,
                          __half* __restrict__ out_lo, int windowed)
{
    int row = blockIdx.x;
    int inRow = row;
    if (windowed) {
        int wdx = row / LW, p = row % LW;
        int wy = wdx / NWIN, wx = wdx % NWIN;
        int iy = p / WINS, ix = p % WINS;
        inRow = (wy * WINS + iy) * 336 + wx * WINS + ix;
    }
    const float* xr = in + (size_t)inRow * DIMC;
    int tid = threadIdx.x;
    float v0 = xr[tid], v1 = xr[tid + 128], v2 = xr[tid + 256];
    float s = v0 + v1 + v2;
    float sq = v0 * v0 + v1 * v1 + v2 * v2;
    #pragma unroll
    for (int o = 16; o > 0; o >>= 1) {
        s  += __shfl_xor_sync(~0u, s, o);
        sq += __shfl_xor_sync(~0u, sq, o);
    }
    __shared__ float ss[4], ssq[4];
    int wid = tid >> 5, lane = tid & 31;
    if (lane == 0) { ss[wid] = s; ssq[wid] = sq; }
    __syncthreads();
    s  = ss[0] + ss[1] + ss[2] + ss[3];
    sq = ssq[0] + ssq[1] + ssq[2] + ssq[3];
    float mean = s * (1.0f / DIMC);
    float var  = sq * (1.0f / DIMC) - mean * mean;
    float inv  = rsqrtf(var + LN_EPS);
    size_t base = (size_t)row * DIMC;
    #pragma unroll
    for (int u = 0; u < 3; u++) {
        int c = tid + u * 128;
        float v = (u == 0 ? v0 : u == 1 ? v1 : v2);
        float y = (v - mean) * inv * w[c] + b[c];
        __half hi = __float2half(y);
        out_hi[base + c] = hi;
        out_lo[base + c] = __float2half(y - __half2float(hi));
    }
}

// ---------------- mma.sync fp16-split GEMM (2-pass) ------------------------
// C[M,N] = (Ah+Al)[M,K] @ B16[N,K]^T ; error = A*Wl ~ 2^-12 relative.
// EPI: 1 qkv scatter   2 proj+residual->g_x2 (unwindow)   3 gelu->big pair
//      4 +extra residual -> C
template <int EPI>
__global__ void __launch_bounds__(256, 2)
mma_gemm(const __half* __restrict__ a_hi, const __half* __restrict__ a_lo,
         const __half* __restrict__ b16,
         const float* __restrict__ bias, float* __restrict__ C,
         int K, const float* __restrict__ extra)
{
    extern __shared__ char smc[];
    uint32_t smb = smem_u32(smc);
    int tid = threadIdx.x;
    int wid = tid >> 5, lane = tid & 31;
    int bn = blockIdx.x, bm = blockIdx.y;
    int wm = wid & 1, wn = wid >> 1;       // warp tile: 64(M) x 32(N)

    const __half* srcs[3] = { a_hi, a_lo, b16 };
    const int NC = K / KC;

    int seg0 = tid * 2;
    int r0 = seg0 >> 2, cc0 = seg0 & 3;
    int r1 = (seg0 + 1) >> 2, cc1 = (seg0 + 1) & 3;

    auto issue = [&](int c, int stg) {
        uint32_t sb = smb + stg * STAGE_B;
        #pragma unroll
        for (int v = 0; v < 3; v++) {
            const __half* src = srcs[v];
            int rowbase = (v < 2 ? bm : bn) * 128;
            cp16(sb + v * TILE_B + tswz(r0, cc0),
                 src + (size_t)(rowbase + r0) * K + c * KC + cc0 * 8);
            cp16(sb + v * TILE_B + tswz(r1, cc1),
                 src + (size_t)(rowbase + r1) * K + c * KC + cc1 * 8);
        }
    };

    float acc[4][4][4] = {};

    issue(0, 0); cp_commit();
    issue(1, 1); cp_commit();
    issue(2, 2); cp_commit();          // NC >= 3 for all our GEMMs

    for (int c = 0; c < NC; c++) {
        cp_wait<2>();
        __syncthreads();

        uint32_t sb = smb + (c % NSTAGE) * STAGE_B;
        #pragma unroll
        for (int ks = 0; ks < 2; ks++) {
            int lrow = lane & 15;
            int lcc = ks * 2 + (lane >> 4);
            uint32_t Ah[4][4], Al[4][4];
            #pragma unroll
            for (int mt = 0; mt < 4; mt++) {
                uint32_t off = tswz(wm * 64 + mt * 16 + lrow, lcc);
                ldsm4(Ah[mt], sb + 0 * TILE_B + off);
                ldsm4(Al[mt], sb + 1 * TILE_B + off);
            }
            #pragma unroll
            for (int tp = 0; tp < 2; tp++) {
                uint32_t boff = tswz(wn * 32 + tp * 16 + lrow, lcc);
                uint32_t bh[4];
                ldsm4(bh, sb + 2 * TILE_B + boff);
                // pass 1: Ah*B — 8 independent accumulators
                #pragma unroll
                for (int mt = 0; mt < 4; mt++) {
                    mma16816(acc[mt][tp * 2 + 0], Ah[mt], bh[0], bh[2]);
                    mma16816(acc[mt][tp * 2 + 1], Ah[mt], bh[1], bh[3]);
                }
                // pass 2: Al*B — same accs, reuse distance 8
                #pragma unroll
                for (int mt = 0; mt < 4; mt++) {
                    mma16816(acc[mt][tp * 2 + 0], Al[mt], bh[0], bh[2]);
                    mma16816(acc[mt][tp * 2 + 1], Al[mt], bh[1], bh[3]);
                }
            }
        }
        __syncthreads();
        if (c + 3 < NC) issue(c + 3, (c + 3) % NSTAGE);
        cp_commit();
    }

    // ---------------- epilogue from C fragments ----------------------------
    #pragma unroll
    for (int mt = 0; mt < 4; mt++) {
        #pragma unroll
        for (int nt = 0; nt < 4; nt++) {
            int mrow = bm * 128 + wm * 64 + mt * 16 + (lane >> 2);
            int col  = bn * 128 + wn * 32 + nt * 8 + 2 * (lane & 3);
            float b0 = bias[col], b1 = bias[col + 1];
            #pragma unroll
            for (int h = 0; h < 2; h++) {
                int m = mrow + h * 8;
                float v0 = acc[mt][nt][2 * h + 0] + b0;
                float v1 = acc[mt][nt][2 * h + 1] + b1;

                if (EPI == 1) {
                    int part = col / 384;
                    int c0 = col % 384;
                    int head = c0 / 64, d0 = c0 % 64;
                    float* dst = (part == 0) ? g_q : (part == 1) ? g_k : g_v;
                    int wdx = m / LW, p = m % LW;
                    float2* o = (float2*)(dst + ((size_t)(wdx * NHEADS + head) * LW + p) * HD + d0);
                    *o = make_float2(v0, v1);
                } else if (EPI == 2) {
                    int wdx = m / LW, p = m % LW;
                    int wy = wdx / NWIN, wx = wdx % NWIN;
                    int iy = p / WINS, ix = p % WINS;
                    int pix = (wy * WINS + iy) * 336 + wx * WINS + ix;
                    const float2 xr = *(const float2*)(extra + (size_t)pix * DIMC + col);
                    *(float2*)(g_x2 + (size_t)pix * DIMC + col) =
                        make_float2(v0 + xr.x, v1 + xr.y);
                } else if (EPI == 3) {
                    float g0 = gelu_exact(v0), g1 = gelu_exact(v1);
                    __half h0 = __float2half(g0);
                    __half h1 = __float2half(g1);
                    *(__half2*)(g_ba_hi + (size_t)m * HIDDEN + col) = __halves2half2(h0, h1);
                    *(__half2*)(g_ba_lo + (size_t)m * HIDDEN + col) =
                        __halves2half2(__float2half(g0 - __half2float(h0)),
                                       __float2half(g1 - __half2float(h1)));
                } else { // EPI == 4
                    const float2 xr = *(const float2*)(extra + (size_t)m * DIMC + col);
                    *(float2*)(C + (size_t)m * DIMC + col) =
                        make_float2(v0 + xr.x, v1 + xr.y);
                }
            }
        }
    }
}

// ---------------- attention scores: S = scale*q@k^T + rel_h + rel_w --------
__global__ void score_kernel(const float* __restrict__ rph, const float* __restrict__ rpw)
{
    extern __shared__ float smf[];
    float* qs   = smf;
    float* ks   = smf + 64 * 200;
    float* relh = ks + 64 * 200;
    float* relw = relh + LW * WINS;

    int wh = blockIdx.x;
    int tid = threadIdx.x;
    const float* qg = g_q + (size_t)wh * LW * HD;
    const float* kg = g_k + (size_t)wh * LW * HD;

    for (int i = tid; i < LW * 16; i += 256) {
        int p = i >> 4, cg = i & 15;
        float4 a = *(const float4*)(qg + p * HD + cg * 4);
        qs[(cg * 4 + 0) * 200 + p] = a.x; qs[(cg * 4 + 1) * 200 + p] = a.y;
        qs[(cg * 4 + 2) * 200 + p] = a.z; qs[(cg * 4 + 3) * 200 + p] = a.w;
        float4 c = *(const float4*)(kg + p * HD + cg * 4);
        ks[(cg * 4 + 0) * 200 + p] = c.x; ks[(cg * 4 + 1) * 200 + p] = c.y;
        ks[(cg * 4 + 2) * 200 + p] = c.z; ks[(cg * 4 + 3) * 200 + p] = c.w;
    }
    __syncthreads();

    for (int i = tid; i < LW * WINS; i += 256) {
        int qi = i / WINS, kq = i % WINS;
        int iy = qi / WINS, ix = qi % WINS;
        const float* rh = rph + (iy - kq + 13) * HD;
        const float* rw = rpw + (ix - kq + 13) * HD;
        float ah = 0.f, aw = 0.f;
        #pragma unroll 8
        for (int c = 0; c < HD; c++) {
            float qv = qs[c * 200 + qi];
            ah += qv * rh[c];
            aw += qv * rw[c];
        }
        relh[i] = ah; relw[i] = aw;
    }
    __syncthreads();

    float* Pg = g_P + (size_t)wh * LL;
    for (int t = tid; t < 49 * 49; t += 256) {
        int ti = t / 49, tj = t % 49;
        int qi0 = ti * 4, ki0 = tj * 4;
        float acc[4][4] = {};
        #pragma unroll 8
        for (int c = 0; c < HD; c++) {
            float4 qv = *(float4*)&qs[c * 200 + qi0];
            float4 kv = *(float4*)&ks[c * 200 + ki0];
            acc[0][0] += qv.x * kv.x; acc[0][1] += qv.x * kv.y; acc[0][2] += qv.x * kv.z; acc[0][3] += qv.x * kv.w;
            acc[1][0] += qv.y * kv.x; acc[1][1] += qv.y * kv.y; acc[1][2] += qv.y * kv.z; acc[1][3] += qv.y * kv.w;
            acc[2][0] += qv.z * kv.x; acc[2][1] += qv.z * kv.y; acc[2][2] += qv.z * kv.z; acc[2][3] += qv.z * kv.w;
            acc[3][0] += qv.w * kv.x; acc[3][1] += qv.w * kv.y; acc[3][2] += qv.w * kv.z; acc[3][3] += qv.w * kv.w;
        }
        #pragma unroll
        for (int i = 0; i < 4; i++) {
            int qi = qi0 + i;
            float4 sv;
            float* svp = (float*)&sv;
            #pragma unroll
            for (int j = 0; j < 4; j++) {
                int ki = ki0 + j;
                int ky = ki / WINS, kx = ki % WINS;
                svp[j] = acc[i][j] * ATT_SCALE + relh[qi * WINS + ky] + relw[qi * WINS + kx];
            }
            *(float4*)(Pg + (size_t)qi * LW + ki0) = sv;
        }
    }
}

// ------- fused softmax + P@V; writes attn-out as fp16 hi/lo pair -----------
__global__ void av_kernel()
{
    extern __shared__ float smf[];
    float* vs = smf;
    float* Ps = smf + LW * HD;
    int wh = blockIdx.x;
    int tid = threadIdx.x;
    const float* vg = g_v + (size_t)wh * LW * HD;
    const float* Pg = g_P + (size_t)wh * LL;

    for (int i = tid; i < LW * HD / 4; i += 256)
        ((float4*)vs)[i] = ((const float4*)vg)[i];
    for (int i = tid; i < LL / 4; i += 256)
        ((float4*)Ps)[i] = ((const float4*)Pg)[i];
    __syncthreads();

    int warp = tid >> 5, lane = tid & 31;
    for (int r = warp; r < LW; r += 8) {
        float* row = Ps + r * LW;
        float v[7];
        float mx = -1e30f;
        #pragma unroll
        for (int j = 0; j < 7; j++) {
            int idx = lane + 32 * j;
            v[j] = (idx < LW) ? row[idx] : -1e30f;
            mx = fmaxf(mx, v[j]);
        }
        #pragma unroll
        for (int o = 16; o > 0; o >>= 1) mx = fmaxf(mx, __shfl_xor_sync(~0u, mx, o));
        float s = 0.f;
        #pragma unroll
        for (int j = 0; j < 7; j++) { v[j] = expf(v[j] - mx); s += v[j]; }
        #pragma unroll
        for (int o = 16; o > 0; o >>= 1) s += __shfl_xor_sync(~0u, s, o);
        float inv = 1.0f / s;
        #pragma unroll
        for (int j = 0; j < 7; j++) {
            int idx = lane + 32 * j;
            if (idx < LW) row[idx] = v[j] * inv;
        }
    }
    __syncthreads();

    if (tid < 196) {
        int qt = tid >> 2, dq = tid & 3;
        int qi0 = qt * 4, d0 = dq * 16;
        float4 acc[4][4] = {};
        for (int ki = 0; ki < LW; ki++) {
            float p0 = Ps[(qi0 + 0) * LW + ki];
            float p1 = Ps[(qi0 + 1) * LW + ki];
            float p2 = Ps[(qi0 + 2) * LW + ki];
            float p3 = Ps[(qi0 + 3) * LW + ki];
            const float4* vrow = (const float4*)(vs + ki * HD + d0);
            #pragma unroll
            for (int j = 0; j < 4; j++) {
                float4 vv = vrow[j];
                acc[0][j].x += p0 * vv.x; acc[0][j].y += p0 * vv.y; acc[0][j].z += p0 * vv.z; acc[0][j].w += p0 * vv.w;
                acc[1][j].x += p1 * vv.x; acc[1][j].y += p1 * vv.y; acc[1][j].z += p1 * vv.z; acc[1][j].w += p1 * vv.w;
                acc[2][j].x += p2 * vv.x; acc[2][j].y += p2 * vv.y; acc[2][j].z += p2 * vv.z; acc[2][j].w += p2 * vv.w;
                acc[3][j].x += p3 * vv.x; acc[3][j].y += p3 * vv.y; acc[3][j].z += p3 * vv.z; acc[3][j].w += p3 * vv.w;
            }
        }
        int wdx = wh / NHEADS, h = wh % NHEADS;
        #pragma unroll
        for (int i = 0; i < 4; i++) {
            size_t base = ((size_t)wdx * LW + qi0 + i) * DIMC + h * HD + d0;
            #pragma unroll
            for (int j = 0; j < 4; j++) {
                const float* a = (const float*)&acc[i][j];
                #pragma unroll
                for (int e = 0; e < 4; e++) {
                    float v = a[e];
                    __half hi = __float2half(v);
                    g_sa_hi[base + 4 * j + e] = hi;
                    g_sa_lo[base + 4 * j + e] = __float2half(v - __half2float(hi));
                }
            }
        }
    }
}

// ---------------- launch ----------------------------------------------------
extern "C" void kernel_launch(void* const* d_in, const int* in_sizes, int n_in,
                              void* d_out, int out_size)
{
    (void)in_sizes; (void)n_in; (void)out_size;
    const float* x      = (const float*)d_in[0];
    const float* qkv_w  = (const float*)d_in[1];
    const float* qkv_b  = (const float*)d_in[2];
    const float* proj_w = (const float*)d_in[3];
    const float* proj_b = (const float*)d_in[4];
    const float* rph    = (const float*)d_in[5];
    const float* rpw    = (const float*)d_in[6];
    const float* n1w    = (const float*)d_in[7];
    const float* n1b    = (const float*)d_in[8];
    const float* n2w    = (const float*)d_in[9];
    const float* n2b    = (const float*)d_in[10];
    const float* fc1w   = (const float*)d_in[11];
    const float* fc1b   = (const float*)d_in[12];
    const float* fc2w   = (const float*)d_in[13];
    const float* fc2b   = (const float*)d_in[14];
    float* out = (float*)d_out;

    cudaFuncSetAttribute(score_kernel, cudaFuncAttributeMaxDynamicSharedMemorySize, SCORE_SMEM);
    cudaFuncSetAttribute(av_kernel,    cudaFuncAttributeMaxDynamicSharedMemorySize, AV_SMEM);
    cudaFuncSetAttribute(mma_gemm<1>,  cudaFuncAttributeMaxDynamicSharedMemorySize, GEMM_SMEM);
    cudaFuncSetAttribute(mma_gemm<2>,  cudaFuncAttributeMaxDynamicSharedMemorySize, GEMM_SMEM);
    cudaFuncSetAttribute(mma_gemm<3>,  cudaFuncAttributeMaxDynamicSharedMemorySize, GEMM_SMEM);
    cudaFuncSetAttribute(mma_gemm<4>,  cudaFuncAttributeMaxDynamicSharedMemorySize, GEMM_SMEM);

    void* p;
    cudaGetSymbolAddress(&p, g_sa_hi);   __half* sa_hi = (__half*)p;
    cudaGetSymbolAddress(&p, g_sa_lo);   __half* sa_lo = (__half*)p;
    cudaGetSymbolAddress(&p, g_ba_hi);   __half* ba_hi = (__half*)p;
    cudaGetSymbolAddress(&p, g_ba_lo);   __half* ba_lo = (__half*)p;
    cudaGetSymbolAddress(&p, g_x2);      float* x2p = (float*)p;
    cudaGetSymbolAddress(&p, g_wqkv);    __half* wqkv = (__half*)p;
    cudaGetSymbolAddress(&p, g_wproj);   __half* wproj = (__half*)p;
    cudaGetSymbolAddress(&p, g_wfc1);    __half* wfc1 = (__half*)p;
    cudaGetSymbolAddress(&p, g_wfc2);    __half* wfc2 = (__half*)p;

    // 0. fused transpose of all four weights -> fp16 [N][K]
    transpose_all<<<1728, 256>>>(qkv_w, proj_w, fc1w, fc2w);
    // 1. LN1 (pixel -> windowed order), fp16 pair
    ln_kernel<<<TOK, 128>>>(x, n1w, n1b, sa_hi, sa_lo, 1);
    // 2. QKV GEMM -> q/k/v fp32 head-major
    mma_gemm<1><<<dim3(1152/TNN, TOK/TMM), 256, GEMM_SMEM>>>(sa_hi, sa_lo, wqkv,
                                                             qkv_b, nullptr, 384, nullptr);
    // 3. scores + rel pos
    score_kernel<<<WH, 256, SCORE_SMEM>>>(rph, rpw);
    // 4. fused softmax + P@V -> attnout fp16 pair
    av_kernel<<<WH, 256, AV_SMEM>>>();
    // 5. proj + residual (unwindow) -> g_x2 fp32
    mma_gemm<2><<<dim3(384/TNN, TOK/TMM), 256, GEMM_SMEM>>>(sa_hi, sa_lo, wproj,
                                                            proj_b, nullptr, 384, x);
    // 6. LN2 -> fp16 pair (pixel order)
    ln_kernel<<<TOK, 128>>>(x2p, n2w, n2b, sa_hi, sa_lo, 0);
    // 7. fc1 + gelu -> big fp16 pair
    mma_gemm<3><<<dim3(1536/TNN, TOK/TMM), 256, GEMM_SMEM>>>(sa_hi, sa_lo, wfc1,
                                                             fc1b, nullptr, 384, nullptr);
    // 8. fc2 + residual -> out
    mma_gemm<4><<<dim3(384/TNN, TOK/TMM), 256, GEMM_SMEM>>>(ba_hi, ba_lo, wfc2,
                                                            fc2b, out, 1536, x2p);
}

// round 16
// speedup vs baseline: 1.3765x; 1.3765x over previous
#include <cuda_runtime.h>
#include <cuda_bf16.h>
#include <math.h>
#include <stdint.h>

#define DIMC 384
#define NHEADS 6
#define HD 64
#define WINS 14
#define NWIN 24
#define NW 576
#define LW 196
#define TOK (NW*LW)      // 112896
#define WH (NW*NHEADS)   // 3456
#define LL (LW*LW)
#define HIDDEN 1536
#define LN_EPS 1e-5f
#define ATT_SCALE 0.125f

#define SCORE_SMEM ((64*200*2 + LW*WINS*2) * 4)
#define AV_SMEM ((LW*HD + LL) * 4)

// ---------------- mma.sync GEMM geometry -----------------------------------
#define TMM 128
#define TNN 128
#define KC 32                       // bf16 K per chunk
#define TILE_B 8192                 // 128 rows * 64 B
#define STAGE_B (4 * TILE_B)        // Ah, Al, Bh, Bl
#define NSTAGE 3
#define GEMM_SMEM (NSTAGE * STAGE_B)  // 98304

// ---------------- scratch --------------------------------------------------
__device__ float g_q[(size_t)TOK * DIMC];
__device__ float g_k[(size_t)TOK * DIMC];
__device__ float g_v[(size_t)TOK * DIMC];
__device__ float g_P[(size_t)WH * LL];
__device__ float g_x2[(size_t)TOK * DIMC];
__device__ float g_dummy[32];
__device__ __nv_bfloat16 g_sa_hi[(size_t)TOK * DIMC];
__device__ __nv_bfloat16 g_sa_lo[(size_t)TOK * DIMC];
__device__ __nv_bfloat16 g_ba_hi[(size_t)TOK * HIDDEN];
__device__ __nv_bfloat16 g_ba_lo[(size_t)TOK * HIDDEN];
__device__ __nv_bfloat16 g_wqkv_hi[1152 * 384], g_wqkv_lo[1152 * 384];
__device__ __nv_bfloat16 g_wproj_hi[384 * 384], g_wproj_lo[384 * 384];
__device__ __nv_bfloat16 g_wfc1_hi[1536 * 384], g_wfc1_lo[1536 * 384];
__device__ __nv_bfloat16 g_wfc2_hi[384 * 1536], g_wfc2_lo[384 * 1536];

// ---------------- PTX helpers ----------------------------------------------
__device__ __forceinline__ uint32_t smem_u32(const void* p)
{ return (uint32_t)__cvta_generic_to_shared(p); }

__device__ __forceinline__ void cp16(uint32_t dst, const void* src)
{ asm volatile("cp.async.cg.shared.global [%0], [%1], 16;" :: "r"(dst), "l"(src)); }
__device__ __forceinline__ void cp_commit()
{ asm volatile("cp.async.commit_group;" ::: "memory"); }
template <int N> __device__ __forceinline__ void cp_wait()
{ asm volatile("cp.async.wait_group %0;" :: "n"(N) : "memory"); }

__device__ __forceinline__ void ldsm4(uint32_t* r, uint32_t a)
{
    asm volatile("ldmatrix.sync.aligned.m8n8.x4.shared.b16 {%0,%1,%2,%3}, [%4];"
                 : "=r"(r[0]), "=r"(r[1]), "=r"(r[2]), "=r"(r[3]) : "r"(a));
}

__device__ __forceinline__ void mma16816(float* c, const uint32_t* a, uint32_t b0, uint32_t b1)
{
    asm volatile("mma.sync.aligned.m16n8k16.row.col.f32.bf16.bf16.f32 "
                 "{%0,%1,%2,%3}, {%4,%5,%6,%7}, {%8,%9}, {%0,%1,%2,%3};"
                 : "+f"(c[0]), "+f"(c[1]), "+f"(c[2]), "+f"(c[3])
                 : "r"(a[0]), "r"(a[1]), "r"(a[2]), "r"(a[3]), "r"(b0), "r"(b1));
}

__device__ __forceinline__ float gelu_exact(float v)
{ return 0.5f * v * (1.0f + erff(v * 0.70710678118654752f)); }

// swizzled byte offset within one 128x(64B) tile
__device__ __forceinline__ uint32_t tswz(int r, int cc)
{ return (uint32_t)(r * 64 + ((cc ^ ((r >> 1) & 3)) << 4)); }

// ---------------- dummy (launch-order shim so ncu profiles the GEMM) -------
__global__ void dummy_kernel() { if (threadIdx.x < 32) g_dummy[threadIdx.x] = 0.f; }

// ---- fused weight transpose -> bf16 hi/lo wT[n][k] (all four weights) -----
// tiles: qkv 432, proj 144, fc1 576, fc2 576  (32x32 tiles)
__global__ void __launch_bounds__(256)
transpose_all(const float* __restrict__ w0, const float* __restrict__ w1,
              const float* __restrict__ w2, const float* __restrict__ w3)
{
    __shared__ float tile[32][33];
    int bid = blockIdx.x;
    const float* src; __nv_bfloat16* dhi; __nv_bfloat16* dlo; int K, N, local;
    if (bid < 432)       { src = w0; dhi = g_wqkv_hi;  dlo = g_wqkv_lo;  K = 384;  N = 1152; local = bid; }
    else if (bid < 576)  { src = w1; dhi = g_wproj_hi; dlo = g_wproj_lo; K = 384;  N = 384;  local = bid - 432; }
    else if (bid < 1152) { src = w2; dhi = g_wfc1_hi;  dlo = g_wfc1_lo;  K = 384;  N = 1536; local = bid - 576; }
    else                 { src = w3; dhi = g_wfc2_hi;  dlo = g_wfc2_lo;  K = 1536; N = 384;  local = bid - 1152; }
    int ntn = N / 32;
    int by = local / ntn, bx = local % ntn;
    int tx = threadIdx.x & 31, ty = threadIdx.x >> 5;
    #pragma unroll
    for (int i = 0; i < 4; i++) {
        int k = by * 32 + ty + i * 8;
        int n = bx * 32 + tx;
        tile[ty + i * 8][tx] = src[(size_t)k * N + n];
    }
    __syncthreads();
    #pragma unroll
    for (int i = 0; i < 4; i++) {
        int n = bx * 32 + ty + i * 8;
        int k = by * 32 + tx;
        float v = tile[tx][ty + i * 8];
        __nv_bfloat16 hi = __float2bfloat16(v);
        dhi[(size_t)n * K + k] = hi;
        dlo[(size_t)n * K + k] = __float2bfloat16(v - __bfloat162float(hi));
    }
}

// ---------------- LayerNorm -> bf16 hi/lo pair -----------------------------
__global__ void ln_kernel(const float* __restrict__ in, const float* __restrict__ w,
                          const float* __restrict__ b,
                          __nv_bfloat16* __restrict__ out_hi,
                          __nv_bfloat16* __restrict__ out_lo, int windowed)
{
    int row = blockIdx.x;
    int inRow = row;
    if (windowed) {
        int wdx = row / LW, p = row % LW;
        int wy = wdx / NWIN, wx = wdx % NWIN;
        int iy = p / WINS, ix = p % WINS;
        inRow = (wy * WINS + iy) * 336 + wx * WINS + ix;
    }
    const float* xr = in + (size_t)inRow * DIMC;
    int tid = threadIdx.x;
    float v0 = xr[tid], v1 = xr[tid + 128], v2 = xr[tid + 256];
    float s = v0 + v1 + v2;
    float sq = v0 * v0 + v1 * v1 + v2 * v2;
    #pragma unroll
    for (int o = 16; o > 0; o >>= 1) {
        s  += __shfl_xor_sync(~0u, s, o);
        sq += __shfl_xor_sync(~0u, sq, o);
    }
    __shared__ float ss[4], ssq[4];
    int wid = tid >> 5, lane = tid & 31;
    if (lane == 0) { ss[wid] = s; ssq[wid] = sq; }
    __syncthreads();
    s  = ss[0] + ss[1] + ss[2] + ss[3];
    sq = ssq[0] + ssq[1] + ssq[2] + ssq[3];
    float mean = s * (1.0f / DIMC);
    float var  = sq * (1.0f / DIMC) - mean * mean;
    float inv  = rsqrtf(var + LN_EPS);
    size_t base = (size_t)row * DIMC;
    #pragma unroll
    for (int u = 0; u < 3; u++) {
        int c = tid + u * 128;
        float v = (u == 0 ? v0 : u == 1 ? v1 : v2);
        float y = (v - mean) * inv * w[c] + b[c];
        __nv_bfloat16 hi = __float2bfloat16(y);
        out_hi[base + c] = hi;
        out_lo[base + c] = __float2bfloat16(y - __bfloat162float(hi));
    }
}

// ---------------- mma.sync bf16-split GEMM (3-pass, R11 config) ------------
// EPI: 1 qkv scatter   2 proj+residual->g_x2 (unwindow)   3 gelu->big pair
//      4 +extra residual -> C
template <int EPI>
__global__ void __launch_bounds__(256, 2)
mma_gemm(const __nv_bfloat16* __restrict__ a_hi, const __nv_bfloat16* __restrict__ a_lo,
         const __nv_bfloat16* __restrict__ b_hi, const __nv_bfloat16* __restrict__ b_lo,
         const float* __restrict__ bias, float* __restrict__ C,
         int K, const float* __restrict__ extra)
{
    extern __shared__ char smc[];
    uint32_t smb = smem_u32(smc);
    int tid = threadIdx.x;
    int wid = tid >> 5, lane = tid & 31;
    int bn = blockIdx.x, bm = blockIdx.y;
    int wm = wid & 1, wn = wid >> 1;       // warp tile: 64(M) x 32(N)

    const __nv_bfloat16* srcs[4] = { a_hi, a_lo, b_hi, b_lo };
    const int NC = K / KC;

    int seg0 = tid * 2;
    int r0 = seg0 >> 2, cc0 = seg0 & 3;
    int r1 = (seg0 + 1) >> 2, cc1 = (seg0 + 1) & 3;

    auto issue = [&](int c, int stg) {
        uint32_t sb = smb + stg * STAGE_B;
        #pragma unroll
        for (int v = 0; v < 4; v++) {
            const __nv_bfloat16* src = srcs[v];
            int rowbase = (v < 2 ? bm : bn) * 128;
            cp16(sb + v * TILE_B + tswz(r0, cc0),
                 src + (size_t)(rowbase + r0) * K + c * KC + cc0 * 8);
            cp16(sb + v * TILE_B + tswz(r1, cc1),
                 src + (size_t)(rowbase + r1) * K + c * KC + cc1 * 8);
        }
    };

    float acc[4][4][4] = {};

    issue(0, 0); cp_commit();
    issue(1, 1); cp_commit();
    issue(2, 2); cp_commit();          // NC >= 3 for all our GEMMs

    for (int c = 0; c < NC; c++) {
        cp_wait<2>();
        __syncthreads();

        uint32_t sb = smb + (c % NSTAGE) * STAGE_B;
        #pragma unroll
        for (int ks = 0; ks < 2; ks++) {
            int lrow = lane & 15;
            int lcc = ks * 2 + (lane >> 4);
            uint32_t Ah[4][4], Al[4][4];
            #pragma unroll
            for (int mt = 0; mt < 4; mt++) {
                uint32_t off = tswz(wm * 64 + mt * 16 + lrow, lcc);
                ldsm4(Ah[mt], sb + 0 * TILE_B + off);
                ldsm4(Al[mt], sb + 1 * TILE_B + off);
            }
            #pragma unroll
            for (int tp = 0; tp < 2; tp++) {
                uint32_t boff = tswz(wn * 32 + tp * 16 + lrow, lcc);
                uint32_t bh[4];
                ldsm4(bh, sb + 2 * TILE_B + boff);
                #pragma unroll
                for (int mt = 0; mt < 4; mt++) {
                    mma16816(acc[mt][tp * 2 + 0], Ah[mt], bh[0], bh[2]);
                    mma16816(acc[mt][tp * 2 + 1], Ah[mt], bh[1], bh[3]);
                }
                #pragma unroll
                for (int mt = 0; mt < 4; mt++) {
                    mma16816(acc[mt][tp * 2 + 0], Al[mt], bh[0], bh[2]);
                    mma16816(acc[mt][tp * 2 + 1], Al[mt], bh[1], bh[3]);
                }
                uint32_t bl[4];
                ldsm4(bl, sb + 3 * TILE_B + boff);
                #pragma unroll
                for (int mt = 0; mt < 4; mt++) {
                    mma16816(acc[mt][tp * 2 + 0], Ah[mt], bl[0], bl[2]);
                    mma16816(acc[mt][tp * 2 + 1], Ah[mt], bl[1], bl[3]);
                }
            }
        }
        __syncthreads();
        if (c + 3 < NC) issue(c + 3, (c + 3) % NSTAGE);
        cp_commit();
    }

    // ---------------- epilogue from C fragments ----------------------------
    #pragma unroll
    for (int mt = 0; mt < 4; mt++) {
        #pragma unroll
        for (int nt = 0; nt < 4; nt++) {
            int mrow = bm * 128 + wm * 64 + mt * 16 + (lane >> 2);
            int col  = bn * 128 + wn * 32 + nt * 8 + 2 * (lane & 3);
            float b0 = bias[col], b1 = bias[col + 1];
            #pragma unroll
            for (int h = 0; h < 2; h++) {
                int m = mrow + h * 8;
                float v0 = acc[mt][nt][2 * h + 0] + b0;
                float v1 = acc[mt][nt][2 * h + 1] + b1;

                if (EPI == 1) {
                    int part = col / 384;
                    int c0 = col % 384;
                    int head = c0 / 64, d0 = c0 % 64;
                    float* dst = (part == 0) ? g_q : (part == 1) ? g_k : g_v;
                    int wdx = m / LW, p = m % LW;
                    float2* o = (float2*)(dst + ((size_t)(wdx * NHEADS + head) * LW + p) * HD + d0);
                    *o = make_float2(v0, v1);
                } else if (EPI == 2) {
                    int wdx = m / LW, p = m % LW;
                    int wy = wdx / NWIN, wx = wdx % NWIN;
                    int iy = p / WINS, ix = p % WINS;
                    int pix = (wy * WINS + iy) * 336 + wx * WINS + ix;
                    const float2 xr = *(const float2*)(extra + (size_t)pix * DIMC + col);
                    *(float2*)(g_x2 + (size_t)pix * DIMC + col) =
                        make_float2(v0 + xr.x, v1 + xr.y);
                } else if (EPI == 3) {
                    float g0 = gelu_exact(v0), g1 = gelu_exact(v1);
                    __nv_bfloat16 h0 = __float2bfloat16(g0);
                    __nv_bfloat16 h1 = __float2bfloat16(g1);
                    __nv_bfloat162* ohi = (__nv_bfloat162*)(g_ba_hi + (size_t)m * HIDDEN + col);
                    __nv_bfloat162* olo = (__nv_bfloat162*)(g_ba_lo + (size_t)m * HIDDEN + col);
                    *ohi = __nv_bfloat162(h0, h1);
                    *olo = __nv_bfloat162(__float2bfloat16(g0 - __bfloat162float(h0)),
                                          __float2bfloat16(g1 - __bfloat162float(h1)));
                } else { // EPI == 4
                    const float2 xr = *(const float2*)(extra + (size_t)m * DIMC + col);
                    *(float2*)(C + (size_t)m * DIMC + col) =
                        make_float2(v0 + xr.x, v1 + xr.y);
                }
            }
        }
    }
}

// ---------------- attention scores: S = scale*q@k^T + rel_h + rel_w --------
__global__ void score_kernel(const float* __restrict__ rph, const float* __restrict__ rpw)
{
    extern __shared__ float smf[];
    float* qs   = smf;
    float* ks   = smf + 64 * 200;
    float* relh = ks + 64 * 200;
    float* relw = relh + LW * WINS;

    int wh = blockIdx.x;
    int tid = threadIdx.x;
    const float* qg = g_q + (size_t)wh * LW * HD;
    const float* kg = g_k + (size_t)wh * LW * HD;

    for (int i = tid; i < LW * 16; i += 256) {
        int p = i >> 4, cg = i & 15;
        float4 a = *(const float4*)(qg + p * HD + cg * 4);
        qs[(cg * 4 + 0) * 200 + p] = a.x; qs[(cg * 4 + 1) * 200 + p] = a.y;
        qs[(cg * 4 + 2) * 200 + p] = a.z; qs[(cg * 4 + 3) * 200 + p] = a.w;
        float4 c = *(const float4*)(kg + p * HD + cg * 4);
        ks[(cg * 4 + 0) * 200 + p] = c.x; ks[(cg * 4 + 1) * 200 + p] = c.y;
        ks[(cg * 4 + 2) * 200 + p] = c.z; ks[(cg * 4 + 3) * 200 + p] = c.w;
    }
    __syncthreads();

    for (int i = tid; i < LW * WINS; i += 256) {
        int qi = i / WINS, kq = i % WINS;
        int iy = qi / WINS, ix = qi % WINS;
        const float* rh = rph + (iy - kq + 13) * HD;
        const float* rw = rpw + (ix - kq + 13) * HD;
        float ah = 0.f, aw = 0.f;
        #pragma unroll 8
        for (int c = 0; c < HD; c++) {
            float qv = qs[c * 200 + qi];
            ah += qv * rh[c];
            aw += qv * rw[c];
        }
        relh[i] = ah; relw[i] = aw;
    }
    __syncthreads();

    float* Pg = g_P + (size_t)wh * LL;
    for (int t = tid; t < 49 * 49; t += 256) {
        int ti = t / 49, tj = t % 49;
        int qi0 = ti * 4, ki0 = tj * 4;
        float acc[4][4] = {};
        #pragma unroll 8
        for (int c = 0; c < HD; c++) {
            float4 qv = *(float4*)&qs[c * 200 + qi0];
            float4 kv = *(float4*)&ks[c * 200 + ki0];
            acc[0][0] += qv.x * kv.x; acc[0][1] += qv.x * kv.y; acc[0][2] += qv.x * kv.z; acc[0][3] += qv.x * kv.w;
            acc[1][0] += qv.y * kv.x; acc[1][1] += qv.y * kv.y; acc[1][2] += qv.y * kv.z; acc[1][3] += qv.y * kv.w;
            acc[2][0] += qv.z * kv.x; acc[2][1] += qv.z * kv.y; acc[2][2] += qv.z * kv.z; acc[2][3] += qv.z * kv.w;
            acc[3][0] += qv.w * kv.x; acc[3][1] += qv.w * kv.y; acc[3][2] += qv.w * kv.z; acc[3][3] += qv.w * kv.w;
        }
        #pragma unroll
        for (int i = 0; i < 4; i++) {
            int qi = qi0 + i;
            float4 sv;
            float* svp = (float*)&sv;
            #pragma unroll
            for (int j = 0; j < 4; j++) {
                int ki = ki0 + j;
                int ky = ki / WINS, kx = ki % WINS;
                svp[j] = acc[i][j] * ATT_SCALE + relh[qi * WINS + ky] + relw[qi * WINS + kx];
            }
            *(float4*)(Pg + (size_t)qi * LW + ki0) = sv;
        }
    }
}

// ------- fused softmax + P@V; writes attn-out as bf16 hi/lo pair -----------
__global__ void av_kernel()
{
    extern __shared__ float smf[];
    float* vs = smf;
    float* Ps = smf + LW * HD;
    int wh = blockIdx.x;
    int tid = threadIdx.x;
    const float* vg = g_v + (size_t)wh * LW * HD;
    const float* Pg = g_P + (size_t)wh * LL;

    for (int i = tid; i < LW * HD / 4; i += 256)
        ((float4*)vs)[i] = ((const float4*)vg)[i];
    for (int i = tid; i < LL / 4; i += 256)
        ((float4*)Ps)[i] = ((const float4*)Pg)[i];
    __syncthreads();

    int warp = tid >> 5, lane = tid & 31;
    for (int r = warp; r < LW; r += 8) {
        float* row = Ps + r * LW;
        float v[7];
        float mx = -1e30f;
        #pragma unroll
        for (int j = 0; j < 7; j++) {
            int idx = lane + 32 * j;
            v[j] = (idx < LW) ? row[idx] : -1e30f;
            mx = fmaxf(mx, v[j]);
        }
        #pragma unroll
        for (int o = 16; o > 0; o >>= 1) mx = fmaxf(mx, __shfl_xor_sync(~0u, mx, o));
        float s = 0.f;
        #pragma unroll
        for (int j = 0; j < 7; j++) { v[j] = expf(v[j] - mx); s += v[j]; }
        #pragma unroll
        for (int o = 16; o > 0; o >>= 1) s += __shfl_xor_sync(~0u, s, o);
        float inv = 1.0f / s;
        #pragma unroll
        for (int j = 0; j < 7; j++) {
            int idx = lane + 32 * j;
            if (idx < LW) row[idx] = v[j] * inv;
        }
    }
    __syncthreads();

    if (tid < 196) {
        int qt = tid >> 2, dq = tid & 3;
        int qi0 = qt * 4, d0 = dq * 16;
        float4 acc[4][4] = {};
        for (int ki = 0; ki < LW; ki++) {
            float p0 = Ps[(qi0 + 0) * LW + ki];
            float p1 = Ps[(qi0 + 1) * LW + ki];
            float p2 = Ps[(qi0 + 2) * LW + ki];
            float p3 = Ps[(qi0 + 3) * LW + ki];
            const float4* vrow = (const float4*)(vs + ki * HD + d0);
            #pragma unroll
            for (int j = 0; j < 4; j++) {
                float4 vv = vrow[j];
                acc[0][j].x += p0 * vv.x; acc[0][j].y += p0 * vv.y; acc[0][j].z += p0 * vv.z; acc[0][j].w += p0 * vv.w;
                acc[1][j].x += p1 * vv.x; acc[1][j].y += p1 * vv.y; acc[1][j].z += p1 * vv.z; acc[1][j].w += p1 * vv.w;
                acc[2][j].x += p2 * vv.x; acc[2][j].y += p2 * vv.y; acc[2][j].z += p2 * vv.z; acc[2][j].w += p2 * vv.w;
                acc[3][j].x += p3 * vv.x; acc[3][j].y += p3 * vv.y; acc[3][j].z += p3 * vv.z; acc[3][j].w += p3 * vv.w;
            }
        }
        int wdx = wh / NHEADS, h = wh % NHEADS;
        #pragma unroll
        for (int i = 0; i < 4; i++) {
            size_t base = ((size_t)wdx * LW + qi0 + i) * DIMC + h * HD + d0;
            #pragma unroll
            for (int j = 0; j < 4; j++) {
                const float* a = (const float*)&acc[i][j];
                #pragma unroll
                for (int e = 0; e < 4; e++) {
                    float v = a[e];
                    __nv_bfloat16 hi = __float2bfloat16(v);
                    g_sa_hi[base + 4 * j + e] = hi;
                    g_sa_lo[base + 4 * j + e] = __float2bfloat16(v - __bfloat162float(hi));
                }
            }
        }
    }
}

// ---------------- launch ----------------------------------------------------
extern "C" void kernel_launch(void* const* d_in, const int* in_sizes, int n_in,
                              void* d_out, int out_size)
{
    (void)in_sizes; (void)n_in; (void)out_size;
    const float* x      = (const float*)d_in[0];
    const float* qkv_w  = (const float*)d_in[1];
    const float* qkv_b  = (const float*)d_in[2];
    const float* proj_w = (const float*)d_in[3];
    const float* proj_b = (const float*)d_in[4];
    const float* rph    = (const float*)d_in[5];
    const float* rpw    = (const float*)d_in[6];
    const float* n1w    = (const float*)d_in[7];
    const float* n1b    = (const float*)d_in[8];
    const float* n2w    = (const float*)d_in[9];
    const float* n2b    = (const float*)d_in[10];
    const float* fc1w   = (const float*)d_in[11];
    const float* fc1b   = (const float*)d_in[12];
    const float* fc2w   = (const float*)d_in[13];
    const float* fc2b   = (const float*)d_in[14];
    float* out = (float*)d_out;

    cudaFuncSetAttribute(score_kernel, cudaFuncAttributeMaxDynamicSharedMemorySize, SCORE_SMEM);
    cudaFuncSetAttribute(av_kernel,    cudaFuncAttributeMaxDynamicSharedMemorySize, AV_SMEM);
    cudaFuncSetAttribute(mma_gemm<1>,  cudaFuncAttributeMaxDynamicSharedMemorySize, GEMM_SMEM);
    cudaFuncSetAttribute(mma_gemm<2>,  cudaFuncAttributeMaxDynamicSharedMemorySize, GEMM_SMEM);
    cudaFuncSetAttribute(mma_gemm<3>,  cudaFuncAttributeMaxDynamicSharedMemorySize, GEMM_SMEM);
    cudaFuncSetAttribute(mma_gemm<4>,  cudaFuncAttributeMaxDynamicSharedMemorySize, GEMM_SMEM);

    void* p;
    cudaGetSymbolAddress(&p, g_sa_hi);   __nv_bfloat16* sa_hi = (__nv_bfloat16*)p;
    cudaGetSymbolAddress(&p, g_sa_lo);   __nv_bfloat16* sa_lo = (__nv_bfloat16*)p;
    cudaGetSymbolAddress(&p, g_ba_hi);   __nv_bfloat16* ba_hi = (__nv_bfloat16*)p;
    cudaGetSymbolAddress(&p, g_ba_lo);   __nv_bfloat16* ba_lo = (__nv_bfloat16*)p;
    cudaGetSymbolAddress(&p, g_x2);      float* x2p = (float*)p;
    cudaGetSymbolAddress(&p, g_wqkv_hi); __nv_bfloat16* wqkv_hi = (__nv_bfloat16*)p;
    cudaGetSymbolAddress(&p, g_wqkv_lo); __nv_bfloat16* wqkv_lo = (__nv_bfloat16*)p;
    cudaGetSymbolAddress(&p, g_wproj_hi);__nv_bfloat16* wproj_hi = (__nv_bfloat16*)p;
    cudaGetSymbolAddress(&p, g_wproj_lo);__nv_bfloat16* wproj_lo = (__nv_bfloat16*)p;
    cudaGetSymbolAddress(&p, g_wfc1_hi); __nv_bfloat16* wfc1_hi = (__nv_bfloat16*)p;
    cudaGetSymbolAddress(&p, g_wfc1_lo); __nv_bfloat16* wfc1_lo = (__nv_bfloat16*)p;
    cudaGetSymbolAddress(&p, g_wfc2_hi); __nv_bfloat16* wfc2_hi = (__nv_bfloat16*)p;
    cudaGetSymbolAddress(&p, g_wfc2_lo); __nv_bfloat16* wfc2_lo = (__nv_bfloat16*)p;

    // launch index:                                          (ncu samples #3)
    // 0. fused transpose of all four weights -> bf16 pair [N][K]
    transpose_all<<<1728, 256>>>(qkv_w, proj_w, fc1w, fc2w);
    // 1. LN1 (pixel -> windowed order), bf16 pair
    ln_kernel<<<TOK, 128>>>(x, n1w, n1b, sa_hi, sa_lo, 1);
    // 2. shim so the profiler lands on the QKV GEMM
    dummy_kernel<<<1, 32>>>();
    // 3. QKV GEMM -> q/k/v fp32 head-major   <-- profiled launch
    mma_gemm<1><<<dim3(1152/TNN, TOK/TMM), 256, GEMM_SMEM>>>(sa_hi, sa_lo, wqkv_hi, wqkv_lo,
                                                             qkv_b, nullptr, 384, nullptr);
    // 4. scores + rel pos
    score_kernel<<<WH, 256, SCORE_SMEM>>>(rph, rpw);
    // 5. fused softmax + P@V -> attnout bf16 pair
    av_kernel<<<WH, 256, AV_SMEM>>>();
    // 6. proj + residual (unwindow) -> g_x2 fp32
    mma_gemm<2><<<dim3(384/TNN, TOK/TMM), 256, GEMM_SMEM>>>(sa_hi, sa_lo, wproj_hi, wproj_lo,
                                                            proj_b, nullptr, 384, x);
    // 7. LN2 -> bf16 pair (pixel order)
    ln_kernel<<<TOK, 128>>>(x2p, n2w, n2b, sa_hi, sa_lo, 0);
    // 8. fc1 + gelu -> big bf16 pair
    mma_gemm<3><<<dim3(1536/TNN, TOK/TMM), 256, GEMM_SMEM>>>(sa_hi, sa_lo, wfc1_hi, wfc1_lo,
                                                             fc1b, nullptr, 384, nullptr);
    // 9. fc2 + residual -> out
    mma_gemm<4><<<dim3(384/TNN, TOK/TMM), 256, GEMM_SMEM>>>(ba_hi, ba_lo, wfc2_hi, wfc2_lo,
                                                            fc2b, out, 1536, x2p);
}

// round 17
// speedup vs baseline: 1.5082x; 1.0957x over previous
#include <cuda_runtime.h>
#include <cuda_bf16.h>
#include <math.h>
#include <stdint.h>

#define DIMC 384
#define NHEADS 6
#define HD 64
#define WINS 14
#define NWIN 24
#define NW 576
#define LW 196
#define TOK (NW*LW)      // 112896
#define WH (NW*NHEADS)   // 3456
#define LL (LW*LW)
#define HIDDEN 1536
#define LN_EPS 1e-5f
#define ATT_SCALE 0.125f

#define SCORE_SMEM ((64*200*2 + LW*WINS*2) * 4)
#define AV_SMEM ((LW*HD + LL) * 4)

// ---------------- mma.sync GEMM geometry -----------------------------------
#define TMM 128
#define TNN 128
#define KC 32                       // bf16 K per chunk
#define TILE_B 8192                 // 128 rows * 64 B
#define STAGE_B (4 * TILE_B)        // Ah, Al, Bh, Bl
#define NSTAGE 3
#define GEMM_SMEM (NSTAGE * STAGE_B)  // 98304

// ---------------- scratch --------------------------------------------------
__device__ float g_q[(size_t)TOK * DIMC];
__device__ float g_k[(size_t)TOK * DIMC];
__device__ float g_v[(size_t)TOK * DIMC];
__device__ float g_P[(size_t)WH * LL];
__device__ float g_x2[(size_t)TOK * DIMC];
__device__ __nv_bfloat16 g_sa_hi[(size_t)TOK * DIMC];
__device__ __nv_bfloat16 g_sa_lo[(size_t)TOK * DIMC];
__device__ __nv_bfloat16 g_ba_hi[(size_t)TOK * HIDDEN];
__device__ __nv_bfloat16 g_ba_lo[(size_t)TOK * HIDDEN];
__device__ __nv_bfloat16 g_wqkv_hi[1152 * 384], g_wqkv_lo[1152 * 384];
__device__ __nv_bfloat16 g_wproj_hi[384 * 384], g_wproj_lo[384 * 384];
__device__ __nv_bfloat16 g_wfc1_hi[1536 * 384], g_wfc1_lo[1536 * 384];
__device__ __nv_bfloat16 g_wfc2_hi[384 * 1536], g_wfc2_lo[384 * 1536];

// ---------------- PTX helpers ----------------------------------------------
__device__ __forceinline__ uint32_t smem_u32(const void* p)
{ return (uint32_t)__cvta_generic_to_shared(p); }

__device__ __forceinline__ void cp16(uint32_t dst, const void* src)
{ asm volatile("cp.async.cg.shared.global [%0], [%1], 16;" :: "r"(dst), "l"(src)); }
__device__ __forceinline__ void cp_commit()
{ asm volatile("cp.async.commit_group;" ::: "memory"); }
template <int N> __device__ __forceinline__ void cp_wait()
{ asm volatile("cp.async.wait_group %0;" :: "n"(N) : "memory"); }

__device__ __forceinline__ void ldsm4(uint32_t* r, uint32_t a)
{
    asm volatile("ldmatrix.sync.aligned.m8n8.x4.shared.b16 {%0,%1,%2,%3}, [%4];"
                 : "=r"(r[0]), "=r"(r[1]), "=r"(r[2]), "=r"(r[3]) : "r"(a));
}

__device__ __forceinline__ void mma16816(float* c, const uint32_t* a, uint32_t b0, uint32_t b1)
{
    asm volatile("mma.sync.aligned.m16n8k16.row.col.f32.bf16.bf16.f32 "
                 "{%0,%1,%2,%3}, {%4,%5,%6,%7}, {%8,%9}, {%0,%1,%2,%3};"
                 : "+f"(c[0]), "+f"(c[1]), "+f"(c[2]), "+f"(c[3])
                 : "r"(a[0]), "r"(a[1]), "r"(a[2]), "r"(a[3]), "r"(b0), "r"(b1));
}

__device__ __forceinline__ float gelu_exact(float v)
{ return 0.5f * v * (1.0f + erff(v * 0.70710678118654752f)); }

// swizzled byte offset within one 128x(64B) tile
__device__ __forceinline__ uint32_t tswz(int r, int cc)
{ return (uint32_t)(r * 64 + ((cc ^ ((r >> 1) & 3)) << 4)); }

// ---- fused weight transpose -> bf16 hi/lo wT[n][k] (all four weights) -----
__global__ void __launch_bounds__(256)
transpose_all(const float* __restrict__ w0, const float* __restrict__ w1,
              const float* __restrict__ w2, const float* __restrict__ w3)
{
    __shared__ float tile[32][33];
    int bid = blockIdx.x;
    const float* src; __nv_bfloat16* dhi; __nv_bfloat16* dlo; int K, N, local;
    if (bid < 432)       { src = w0; dhi = g_wqkv_hi;  dlo = g_wqkv_lo;  K = 384;  N = 1152; local = bid; }
    else if (bid < 576)  { src = w1; dhi = g_wproj_hi; dlo = g_wproj_lo; K = 384;  N = 384;  local = bid - 432; }
    else if (bid < 1152) { src = w2; dhi = g_wfc1_hi;  dlo = g_wfc1_lo;  K = 384;  N = 1536; local = bid - 576; }
    else                 { src = w3; dhi = g_wfc2_hi;  dlo = g_wfc2_lo;  K = 1536; N = 384;  local = bid - 1152; }
    int ntn = N / 32;
    int by = local / ntn, bx = local % ntn;
    int tx = threadIdx.x & 31, ty = threadIdx.x >> 5;
    #pragma unroll
    for (int i = 0; i < 4; i++) {
        int k = by * 32 + ty + i * 8;
        int n = bx * 32 + tx;
        tile[ty + i * 8][tx] = src[(size_t)k * N + n];
    }
    __syncthreads();
    #pragma unroll
    for (int i = 0; i < 4; i++) {
        int n = bx * 32 + ty + i * 8;
        int k = by * 32 + tx;
        float v = tile[tx][ty + i * 8];
        __nv_bfloat16 hi = __float2bfloat16(v);
        dhi[(size_t)n * K + k] = hi;
        dlo[(size_t)n * K + k] = __float2bfloat16(v - __bfloat162float(hi));
    }
}

// ---------------- LayerNorm -> bf16 hi/lo pair -----------------------------
__global__ void ln_kernel(const float* __restrict__ in, const float* __restrict__ w,
                          const float* __restrict__ b,
                          __nv_bfloat16* __restrict__ out_hi,
                          __nv_bfloat16* __restrict__ out_lo, int windowed)
{
    int row = blockIdx.x;
    int inRow = row;
    if (windowed) {
        int wdx = row / LW, p = row % LW;
        int wy = wdx / NWIN, wx = wdx % NWIN;
        int iy = p / WINS, ix = p % WINS;
        inRow = (wy * WINS + iy) * 336 + wx * WINS + ix;
    }
    const float* xr = in + (size_t)inRow * DIMC;
    int tid = threadIdx.x;
    float v0 = xr[tid], v1 = xr[tid + 128], v2 = xr[tid + 256];
    float s = v0 + v1 + v2;
    float sq = v0 * v0 + v1 * v1 + v2 * v2;
    #pragma unroll
    for (int o = 16; o > 0; o >>= 1) {
        s  += __shfl_xor_sync(~0u, s, o);
        sq += __shfl_xor_sync(~0u, sq, o);
    }
    __shared__ float ss[4], ssq[4];
    int wid = tid >> 5, lane = tid & 31;
    if (lane == 0) { ss[wid] = s; ssq[wid] = sq; }
    __syncthreads();
    s  = ss[0] + ss[1] + ss[2] + ss[3];
    sq = ssq[0] + ssq[1] + ssq[2] + ssq[3];
    float mean = s * (1.0f / DIMC);
    float var  = sq * (1.0f / DIMC) - mean * mean;
    float inv  = rsqrtf(var + LN_EPS);
    size_t base = (size_t)row * DIMC;
    #pragma unroll
    for (int u = 0; u < 3; u++) {
        int c = tid + u * 128;
        float v = (u == 0 ? v0 : u == 1 ? v1 : v2);
        float y = (v - mean) * inv * w[c] + b[c];
        __nv_bfloat16 hi = __float2bfloat16(y);
        out_hi[base + c] = hi;
        out_lo[base + c] = __float2bfloat16(y - __bfloat162float(hi));
    }
}

// ---------------- mma.sync bf16-split GEMM (3-pass, R11 config) ------------
// EPI: 1 qkv scatter   2 proj+residual->g_x2 (unwindow)   3 gelu->big pair
//      4 +extra residual -> C
template <int EPI>
__global__ void __launch_bounds__(256, 2)
mma_gemm(const __nv_bfloat16* __restrict__ a_hi, const __nv_bfloat16* __restrict__ a_lo,
         const __nv_bfloat16* __restrict__ b_hi, const __nv_bfloat16* __restrict__ b_lo,
         const float* __restrict__ bias, float* __restrict__ C,
         int K, const float* __restrict__ extra)
{
    extern __shared__ char smc[];
    uint32_t smb = smem_u32(smc);
    int tid = threadIdx.x;
    int wid = tid >> 5, lane = tid & 31;
    int bn = blockIdx.x, bm = blockIdx.y;
    int wm = wid & 1, wn = wid >> 1;       // warp tile: 64(M) x 32(N)

    const __nv_bfloat16* srcs[4] = { a_hi, a_lo, b_hi, b_lo };
    const int NC = K / KC;

    int seg0 = tid * 2;
    int r0 = seg0 >> 2, cc0 = seg0 & 3;
    int r1 = (seg0 + 1) >> 2, cc1 = (seg0 + 1) & 3;

    auto issue = [&](int c, int stg) {
        uint32_t sb = smb + stg * STAGE_B;
        #pragma unroll
        for (int v = 0; v < 4; v++) {
            const __nv_bfloat16* src = srcs[v];
            int rowbase = (v < 2 ? bm : bn) * 128;
            cp16(sb + v * TILE_B + tswz(r0, cc0),
                 src + (size_t)(rowbase + r0) * K + c * KC + cc0 * 8);
            cp16(sb + v * TILE_B + tswz(r1, cc1),
                 src + (size_t)(rowbase + r1) * K + c * KC + cc1 * 8);
        }
    };

    float acc[4][4][4] = {};

    issue(0, 0); cp_commit();
    issue(1, 1); cp_commit();
    issue(2, 2); cp_commit();          // NC >= 3 for all our GEMMs

    for (int c = 0; c < NC; c++) {
        cp_wait<2>();
        __syncthreads();

        uint32_t sb = smb + (c % NSTAGE) * STAGE_B;
        #pragma unroll
        for (int ks = 0; ks < 2; ks++) {
            int lrow = lane & 15;
            int lcc = ks * 2 + (lane >> 4);
            uint32_t Ah[4][4], Al[4][4];
            #pragma unroll
            for (int mt = 0; mt < 4; mt++) {
                uint32_t off = tswz(wm * 64 + mt * 16 + lrow, lcc);
                ldsm4(Ah[mt], sb + 0 * TILE_B + off);
                ldsm4(Al[mt], sb + 1 * TILE_B + off);
            }
            #pragma unroll
            for (int tp = 0; tp < 2; tp++) {
                uint32_t boff = tswz(wn * 32 + tp * 16 + lrow, lcc);
                uint32_t bh[4];
                ldsm4(bh, sb + 2 * TILE_B + boff);
                #pragma unroll
                for (int mt = 0; mt < 4; mt++) {
                    mma16816(acc[mt][tp * 2 + 0], Ah[mt], bh[0], bh[2]);
                    mma16816(acc[mt][tp * 2 + 1], Ah[mt], bh[1], bh[3]);
                }
                #pragma unroll
                for (int mt = 0; mt < 4; mt++) {
                    mma16816(acc[mt][tp * 2 + 0], Al[mt], bh[0], bh[2]);
                    mma16816(acc[mt][tp * 2 + 1], Al[mt], bh[1], bh[3]);
                }
                uint32_t bl[4];
                ldsm4(bl, sb + 3 * TILE_B + boff);
                #pragma unroll
                for (int mt = 0; mt < 4; mt++) {
                    mma16816(acc[mt][tp * 2 + 0], Ah[mt], bl[0], bl[2]);
                    mma16816(acc[mt][tp * 2 + 1], Ah[mt], bl[1], bl[3]);
                }
            }
        }
        __syncthreads();
        if (c + 3 < NC) issue(c + 3, (c + 3) % NSTAGE);
        cp_commit();
    }

    // ---------------- epilogue from C fragments ----------------------------
    #pragma unroll
    for (int mt = 0; mt < 4; mt++) {
        #pragma unroll
        for (int nt = 0; nt < 4; nt++) {
            int mrow = bm * 128 + wm * 64 + mt * 16 + (lane >> 2);
            int col  = bn * 128 + wn * 32 + nt * 8 + 2 * (lane & 3);
            float b0 = bias[col], b1 = bias[col + 1];
            #pragma unroll
            for (int h = 0; h < 2; h++) {
                int m = mrow + h * 8;
                float v0 = acc[mt][nt][2 * h + 0] + b0;
                float v1 = acc[mt][nt][2 * h + 1] + b1;

                if (EPI == 1) {
                    int part = col / 384;
                    int c0 = col % 384;
                    int head = c0 / 64, d0 = c0 % 64;
                    float* dst = (part == 0) ? g_q : (part == 1) ? g_k : g_v;
                    int wdx = m / LW, p = m % LW;
                    float2* o = (float2*)(dst + ((size_t)(wdx * NHEADS + head) * LW + p) * HD + d0);
                    *o = make_float2(v0, v1);
                } else if (EPI == 2) {
                    int wdx = m / LW, p = m % LW;
                    int wy = wdx / NWIN, wx = wdx % NWIN;
                    int iy = p / WINS, ix = p % WINS;
                    int pix = (wy * WINS + iy) * 336 + wx * WINS + ix;
                    const float2 xr = *(const float2*)(extra + (size_t)pix * DIMC + col);
                    *(float2*)(g_x2 + (size_t)pix * DIMC + col) =
                        make_float2(v0 + xr.x, v1 + xr.y);
                } else if (EPI == 3) {
                    float g0 = gelu_exact(v0), g1 = gelu_exact(v1);
                    __nv_bfloat16 h0 = __float2bfloat16(g0);
                    __nv_bfloat16 h1 = __float2bfloat16(g1);
                    __nv_bfloat162* ohi = (__nv_bfloat162*)(g_ba_hi + (size_t)m * HIDDEN + col);
                    __nv_bfloat162* olo = (__nv_bfloat162*)(g_ba_lo + (size_t)m * HIDDEN + col);
                    *ohi = __nv_bfloat162(h0, h1);
                    *olo = __nv_bfloat162(__float2bfloat16(g0 - __bfloat162float(h0)),
                                          __float2bfloat16(g1 - __bfloat162float(h1)));
                } else { // EPI == 4
                    const float2 xr = *(const float2*)(extra + (size_t)m * DIMC + col);
                    *(float2*)(C + (size_t)m * DIMC + col) =
                        make_float2(v0 + xr.x, v1 + xr.y);
                }
            }
        }
    }
}

// ---------------- attention scores (512 threads) ---------------------------
__global__ void __launch_bounds__(512)
score_kernel(const float* __restrict__ rph, const float* __restrict__ rpw)
{
    extern __shared__ float smf[];
    float* qs   = smf;
    float* ks   = smf + 64 * 200;
    float* relh = ks + 64 * 200;
    float* relw = relh + LW * WINS;

    int wh = blockIdx.x;
    int tid = threadIdx.x;
    const float* qg = g_q + (size_t)wh * LW * HD;
    const float* kg = g_k + (size_t)wh * LW * HD;

    for (int i = tid; i < LW * 16; i += 512) {
        int p = i >> 4, cg = i & 15;
        float4 a = *(const float4*)(qg + p * HD + cg * 4);
        qs[(cg * 4 + 0) * 200 + p] = a.x; qs[(cg * 4 + 1) * 200 + p] = a.y;
        qs[(cg * 4 + 2) * 200 + p] = a.z; qs[(cg * 4 + 3) * 200 + p] = a.w;
        float4 c = *(const float4*)(kg + p * HD + cg * 4);
        ks[(cg * 4 + 0) * 200 + p] = c.x; ks[(cg * 4 + 1) * 200 + p] = c.y;
        ks[(cg * 4 + 2) * 200 + p] = c.z; ks[(cg * 4 + 3) * 200 + p] = c.w;
    }
    __syncthreads();

    for (int i = tid; i < LW * WINS; i += 512) {
        int qi = i / WINS, kq = i % WINS;
        int iy = qi / WINS, ix = qi % WINS;
        const float* rh = rph + (iy - kq + 13) * HD;
        const float* rw = rpw + (ix - kq + 13) * HD;
        float ah = 0.f, aw = 0.f;
        #pragma unroll 8
        for (int c = 0; c < HD; c++) {
            float qv = qs[c * 200 + qi];
            ah += qv * rh[c];
            aw += qv * rw[c];
        }
        relh[i] = ah; relw[i] = aw;
    }
    __syncthreads();

    float* Pg = g_P + (size_t)wh * LL;
    for (int t = tid; t < 49 * 49; t += 512) {
        int ti = t / 49, tj = t % 49;
        int qi0 = ti * 4, ki0 = tj * 4;
        float acc[4][4] = {};
        #pragma unroll 8
        for (int c = 0; c < HD; c++) {
            float4 qv = *(float4*)&qs[c * 200 + qi0];
            float4 kv = *(float4*)&ks[c * 200 + ki0];
            acc[0][0] += qv.x * kv.x; acc[0][1] += qv.x * kv.y; acc[0][2] += qv.x * kv.z; acc[0][3] += qv.x * kv.w;
            acc[1][0] += qv.y * kv.x; acc[1][1] += qv.y * kv.y; acc[1][2] += qv.y * kv.z; acc[1][3] += qv.y * kv.w;
            acc[2][0] += qv.z * kv.x; acc[2][1] += qv.z * kv.y; acc[2][2] += qv.z * kv.z; acc[2][3] += qv.z * kv.w;
            acc[3][0] += qv.w * kv.x; acc[3][1] += qv.w * kv.y; acc[3][2] += qv.w * kv.z; acc[3][3] += qv.w * kv.w;
        }
        #pragma unroll
        for (int i = 0; i < 4; i++) {
            int qi = qi0 + i;
            float4 sv;
            float* svp = (float*)&sv;
            #pragma unroll
            for (int j = 0; j < 4; j++) {
                int ki = ki0 + j;
                int ky = ki / WINS, kx = ki % WINS;
                svp[j] = acc[i][j] * ATT_SCALE + relh[qi * WINS + ky] + relw[qi * WINS + kx];
            }
            *(float4*)(Pg + (size_t)qi * LW + ki0) = sv;
        }
    }
}

// ------- fused softmax + P@V (512 threads); bf16 hi/lo output --------------
__global__ void __launch_bounds__(512)
av_kernel()
{
    extern __shared__ float smf[];
    float* vs = smf;
    float* Ps = smf + LW * HD;
    int wh = blockIdx.x;
    int tid = threadIdx.x;
    const float* vg = g_v + (size_t)wh * LW * HD;
    const float* Pg = g_P + (size_t)wh * LL;

    for (int i = tid; i < LW * HD / 4; i += 512)
        ((float4*)vs)[i] = ((const float4*)vg)[i];
    for (int i = tid; i < LL / 4; i += 512)
        ((float4*)Ps)[i] = ((const float4*)Pg)[i];
    __syncthreads();

    int warp = tid >> 5, lane = tid & 31;
    for (int r = warp; r < LW; r += 16) {
        float* row = Ps + r * LW;
        float v[7];
        float mx = -1e30f;
        #pragma unroll
        for (int j = 0; j < 7; j++) {
            int idx = lane + 32 * j;
            v[j] = (idx < LW) ? row[idx] : -1e30f;
            mx = fmaxf(mx, v[j]);
        }
        #pragma unroll
        for (int o = 16; o > 0; o >>= 1) mx = fmaxf(mx, __shfl_xor_sync(~0u, mx, o));
        float s = 0.f;
        #pragma unroll
        for (int j = 0; j < 7; j++) { v[j] = expf(v[j] - mx); s += v[j]; }
        #pragma unroll
        for (int o = 16; o > 0; o >>= 1) s += __shfl_xor_sync(~0u, s, o);
        float inv = 1.0f / s;
        #pragma unroll
        for (int j = 0; j < 7; j++) {
            int idx = lane + 32 * j;
            if (idx < LW) row[idx] = v[j] * inv;
        }
    }
    __syncthreads();

    // P@V: 392 active threads, each 4 q-rows x 8 d-cols
    if (tid < 392) {
        int qt = tid >> 3, dq = tid & 7;
        int qi0 = qt * 4, d0 = dq * 8;
        float4 acc[4][2] = {};
        for (int ki = 0; ki < LW; ki++) {
            float p0 = Ps[(qi0 + 0) * LW + ki];
            float p1 = Ps[(qi0 + 1) * LW + ki];
            float p2 = Ps[(qi0 + 2) * LW + ki];
            float p3 = Ps[(qi0 + 3) * LW + ki];
            const float4* vrow = (const float4*)(vs + ki * HD + d0);
            float4 va = vrow[0], vb = vrow[1];
            acc[0][0].x += p0 * va.x; acc[0][0].y += p0 * va.y; acc[0][0].z += p0 * va.z; acc[0][0].w += p0 * va.w;
            acc[0][1].x += p0 * vb.x; acc[0][1].y += p0 * vb.y; acc[0][1].z += p0 * vb.z; acc[0][1].w += p0 * vb.w;
            acc[1][0].x += p1 * va.x; acc[1][0].y += p1 * va.y; acc[1][0].z += p1 * va.z; acc[1][0].w += p1 * va.w;
            acc[1][1].x += p1 * vb.x; acc[1][1].y += p1 * vb.y; acc[1][1].z += p1 * vb.z; acc[1][1].w += p1 * vb.w;
            acc[2][0].x += p2 * va.x; acc[2][0].y += p2 * va.y; acc[2][0].z += p2 * va.z; acc[2][0].w += p2 * va.w;
            acc[2][1].x += p2 * vb.x; acc[2][1].y += p2 * vb.y; acc[2][1].z += p2 * vb.z; acc[2][1].w += p2 * vb.w;
            acc[3][0].x += p3 * va.x; acc[3][0].y += p3 * va.y; acc[3][0].z += p3 * va.z; acc[3][0].w += p3 * va.w;
            acc[3][1].x += p3 * vb.x; acc[3][1].y += p3 * vb.y; acc[3][1].z += p3 * vb.z; acc[3][1].w += p3 * vb.w;
        }
        int wdx = wh / NHEADS, h = wh % NHEADS;
        #pragma unroll
        for (int i = 0; i < 4; i++) {
            size_t base = ((size_t)wdx * LW + qi0 + i) * DIMC + h * HD + d0;
            #pragma unroll
            for (int j = 0; j < 2; j++) {
                const float* a = (const float*)&acc[i][j];
                #pragma unroll
                for (int e = 0; e < 4; e++) {
                    float v = a[e];
                    __nv_bfloat16 hi = __float2bfloat16(v);
                    g_sa_hi[base + 4 * j + e] = hi;
                    g_sa_lo[base + 4 * j + e] = __float2bfloat16(v - __bfloat162float(hi));
                }
            }
        }
    }
}

// ---------------- launch ----------------------------------------------------
extern "C" void kernel_launch(void* const* d_in, const int* in_sizes, int n_in,
                              void* d_out, int out_size)
{
    (void)in_sizes; (void)n_in; (void)out_size;
    const float* x      = (const float*)d_in[0];
    const float* qkv_w  = (const float*)d_in[1];
    const float* qkv_b  = (const float*)d_in[2];
    const float* proj_w = (const float*)d_in[3];
    const float* proj_b = (const float*)d_in[4];
    const float* rph    = (const float*)d_in[5];
    const float* rpw    = (const float*)d_in[6];
    const float* n1w    = (const float*)d_in[7];
    const float* n1b    = (const float*)d_in[8];
    const float* n2w    = (const float*)d_in[9];
    const float* n2b    = (const float*)d_in[10];
    const float* fc1w   = (const float*)d_in[11];
    const float* fc1b   = (const float*)d_in[12];
    const float* fc2w   = (const float*)d_in[13];
    const float* fc2b   = (const float*)d_in[14];
    float* out = (float*)d_out;

    cudaFuncSetAttribute(score_kernel, cudaFuncAttributeMaxDynamicSharedMemorySize, SCORE_SMEM);
    cudaFuncSetAttribute(av_kernel,    cudaFuncAttributeMaxDynamicSharedMemorySize, AV_SMEM);
    cudaFuncSetAttribute(mma_gemm<1>,  cudaFuncAttributeMaxDynamicSharedMemorySize, GEMM_SMEM);
    cudaFuncSetAttribute(mma_gemm<2>,  cudaFuncAttributeMaxDynamicSharedMemorySize, GEMM_SMEM);
    cudaFuncSetAttribute(mma_gemm<3>,  cudaFuncAttributeMaxDynamicSharedMemorySize, GEMM_SMEM);
    cudaFuncSetAttribute(mma_gemm<4>,  cudaFuncAttributeMaxDynamicSharedMemorySize, GEMM_SMEM);

    void* p;
    cudaGetSymbolAddress(&p, g_sa_hi);   __nv_bfloat16* sa_hi = (__nv_bfloat16*)p;
    cudaGetSymbolAddress(&p, g_sa_lo);   __nv_bfloat16* sa_lo = (__nv_bfloat16*)p;
    cudaGetSymbolAddress(&p, g_ba_hi);   __nv_bfloat16* ba_hi = (__nv_bfloat16*)p;
    cudaGetSymbolAddress(&p, g_ba_lo);   __nv_bfloat16* ba_lo = (__nv_bfloat16*)p;
    cudaGetSymbolAddress(&p, g_x2);      float* x2p = (float*)p;
    cudaGetSymbolAddress(&p, g_wqkv_hi); __nv_bfloat16* wqkv_hi = (__nv_bfloat16*)p;
    cudaGetSymbolAddress(&p, g_wqkv_lo); __nv_bfloat16* wqkv_lo = (__nv_bfloat16*)p;
    cudaGetSymbolAddress(&p, g_wproj_hi);__nv_bfloat16* wproj_hi = (__nv_bfloat16*)p;
    cudaGetSymbolAddress(&p, g_wproj_lo);__nv_bfloat16* wproj_lo = (__nv_bfloat16*)p;
    cudaGetSymbolAddress(&p, g_wfc1_hi); __nv_bfloat16* wfc1_hi = (__nv_bfloat16*)p;
    cudaGetSymbolAddress(&p, g_wfc1_lo); __nv_bfloat16* wfc1_lo = (__nv_bfloat16*)p;
    cudaGetSymbolAddress(&p, g_wfc2_hi); __nv_bfloat16* wfc2_hi = (__nv_bfloat16*)p;
    cudaGetSymbolAddress(&p, g_wfc2_lo); __nv_bfloat16* wfc2_lo = (__nv_bfloat16*)p;

    // launch index (ncu samples #3 -> score_kernel this round)
    // 0. fused transpose of all four weights -> bf16 pair [N][K]
    transpose_all<<<1728, 256>>>(qkv_w, proj_w, fc1w, fc2w);
    // 1. LN1 (pixel -> windowed order), bf16 pair
    ln_kernel<<<TOK, 128>>>(x, n1w, n1b, sa_hi, sa_lo, 1);
    // 2. QKV GEMM -> q/k/v fp32 head-major
    mma_gemm<1><<<dim3(1152/TNN, TOK/TMM), 256, GEMM_SMEM>>>(sa_hi, sa_lo, wqkv_hi, wqkv_lo,
                                                             qkv_b, nullptr, 384, nullptr);
    // 3. scores + rel pos   <-- profiled launch
    score_kernel<<<WH, 512, SCORE_SMEM>>>(rph, rpw);
    // 4. fused softmax + P@V -> attnout bf16 pair
    av_kernel<<<WH, 512, AV_SMEM>>>();
    // 5. proj + residual (unwindow) -> g_x2 fp32
    mma_gemm<2><<<dim3(384/TNN, TOK/TMM), 256, GEMM_SMEM>>>(sa_hi, sa_lo, wproj_hi, wproj_lo,
                                                            proj_b, nullptr, 384, x);
    // 6. LN2 -> bf16 pair (pixel order)
    ln_kernel<<<TOK, 128>>>(x2p, n2w, n2b, sa_hi, sa_lo, 0);
    // 7. fc1 + gelu -> big bf16 pair
    mma_gemm<3><<<dim3(1536/TNN, TOK/TMM), 256, GEMM_SMEM>>>(sa_hi, sa_lo, wfc1_hi, wfc1_lo,
                                                             fc1b, nullptr, 384, nullptr);
    // 8. fc2 + residual -> out
    mma_gemm<4><<<dim3(384/TNN, TOK/TMM), 256, GEMM_SMEM>>>(ba_hi, ba_lo, wfc2_hi, wfc2_lo,
                                                            fc2b, out, 1536, x2p);
}